// round 5
// baseline (speedup 1.0000x reference)
#include <cuda_runtime.h>
#include <cuda_bf16.h>
#include <math_constants.h>

// EdgeAwareLoss: predictions [16,19,512,512] f32, targets [16,512,512] int32
// out: scalar f32 = mean over pixels of CE * (1 + edge)
// edge = any in-bounds 3x3 neighbor label != center label.
//
// Layout trick: grid(1024) x block(256) = 262144 threads = HW exactly.
// Each thread owns one (h,w) and loops over all 16 batch images, so the
// neighbor-offset/boundary math is computed once and reused 16x. All loads
// stay perfectly coalesced (consecutive threads -> consecutive hw).

#define BB 16
#define CC 19
#define HH 512
#define WW 512
#define HW (HH * WW)            // 262144
#define NPIX (BB * HW)          // 4194304
#define TPB 256
#define NBLK (HW / TPB)         // 1024

__device__ double g_partials[NBLK];

__global__ __launch_bounds__(TPB) void edge_loss_main(
    const float* __restrict__ pred, const int* __restrict__ tgt)
{
    const int hw = blockIdx.x * TPB + threadIdx.x;   // 0..HW-1
    const int h  = hw >> 9;
    const int w  = hw & (WW - 1);

    // ---- 3x3 neighbor offsets + validity, computed once ----
    const bool hup = (h > 0), hdn = (h < HH - 1);
    const bool wlf = (w > 0), wrt = (w < WW - 1);
    int   offs[8];
    bool  ok[8];
    offs[0] = hw - WW - 1; ok[0] = hup && wlf;
    offs[1] = hw - WW;     ok[1] = hup;
    offs[2] = hw - WW + 1; ok[2] = hup && wrt;
    offs[3] = hw - 1;      ok[3] = wlf;
    offs[4] = hw + 1;      ok[4] = wrt;
    offs[5] = hw + WW - 1; ok[5] = hdn && wlf;
    offs[6] = hw + WW;     ok[6] = hdn;
    offs[7] = hw + WW + 1; ok[7] = hdn && wrt;

    float acc = 0.f;

    for (int b = 0; b < BB; ++b) {
        // ---- channel values: 19 coalesced strided loads ----
        const float* p = pred + b * (CC * HW) + hw;
        float v[CC];
        float m = -CUDART_INF_F;
#pragma unroll
        for (int c = 0; c < CC; ++c) {
            v[c] = p[c * HW];
            m = fmaxf(m, v[c]);
        }
        float s = 0.f;
#pragma unroll
        for (int c = 0; c < CC; ++c) s += __expf(v[c] - m);
        const float lse = m + __logf(s);

        // ---- target + gather v[t] without dynamic indexing ----
        const int* tb = tgt + b * HW;
        const int t = tb[hw];
        float xt = v[0];
#pragma unroll
        for (int c = 1; c < CC; ++c) xt = (t == c) ? v[c] : xt;
        const float ce = lse - xt;

        // ---- edge mask ----
        int edge = 0;
#pragma unroll
        for (int k = 0; k < 8; ++k)
            edge |= (ok[k] && tb[offs[k]] != t);

        acc += ce * (edge ? 2.0f : 1.0f);
    }

    // ---- block reduction -> g_partials[blockIdx.x] (always overwritten) ----
#pragma unroll
    for (int o = 16; o > 0; o >>= 1) acc += __shfl_xor_sync(0xFFFFFFFFu, acc, o);

    __shared__ float smem[TPB / 32];
    if ((threadIdx.x & 31) == 0) smem[threadIdx.x >> 5] = acc;
    __syncthreads();
    if (threadIdx.x < (TPB / 32)) {
        float x = smem[threadIdx.x];
#pragma unroll
        for (int o = (TPB / 64); o > 0; o >>= 1)
            x += __shfl_xor_sync(0xFFu, x, o);
        if (threadIdx.x == 0) g_partials[blockIdx.x] = (double)x;
    }
}

#define RTPB 1024
__global__ __launch_bounds__(RTPB) void edge_loss_reduce(float* __restrict__ out)
{
    double s = g_partials[threadIdx.x];   // one element per thread, NBLK == RTPB

#pragma unroll
    for (int o = 16; o > 0; o >>= 1) s += __shfl_xor_sync(0xFFFFFFFFu, s, o);

    __shared__ double smem[RTPB / 32];
    if ((threadIdx.x & 31) == 0) smem[threadIdx.x >> 5] = s;
    __syncthreads();
    if (threadIdx.x < 32) {
        double x = smem[threadIdx.x];
#pragma unroll
        for (int o = 16; o > 0; o >>= 1) x += __shfl_xor_sync(0xFFFFFFFFu, x, o);
        if (threadIdx.x == 0) out[0] = (float)(x / (double)NPIX);
    }
}

extern "C" void kernel_launch(void* const* d_in, const int* in_sizes, int n_in,
                              void* d_out, int out_size)
{
    const float* pred = (const float*)d_in[0];
    const int*   tgt  = (const int*)d_in[1];
    float*       out  = (float*)d_out;

    edge_loss_main<<<NBLK, TPB>>>(pred, tgt);
    edge_loss_reduce<<<1, RTPB>>>(out);
}

// round 7
// speedup vs baseline: 1.0691x; 1.0691x over previous
#include <cuda_runtime.h>
#include <cuda_bf16.h>
#include <math_constants.h>

// EdgeAwareLoss: predictions [16,19,512,512] f32, targets [16,512,512] int32
// out: scalar f32 = mean over pixels of CE * (1 + edge)
// edge = any in-bounds 3x3 neighbor label != center label.
//
// R4 main-kernel shape (1 pixel/thread, max parallelism — measured 55us,
// ~76% HBM) + wide 1024-thread single-block reduce (R4's 256-thr reduce
// cost 10.8us; R5 showed wide block is ~2x better, now with 16-way MLP).

#define BB 16
#define CC 19
#define HH 512
#define WW 512
#define HW (HH * WW)            // 262144
#define NPIX (BB * HW)          // 4194304
#define TPB 256
#define NBLK (NPIX / TPB)       // 16384

__device__ float g_partials[NBLK];

__global__ __launch_bounds__(TPB) void edge_loss_main(
    const float* __restrict__ pred, const int* __restrict__ tgt)
{
    const int idx = blockIdx.x * TPB + threadIdx.x;
    const int hw = idx & (HW - 1);
    const int b  = idx >> 18;
    const int h  = hw >> 9;
    const int w  = hw & (WW - 1);

    // ---- channel values: 19 coalesced strided loads, kept in registers ----
    const float* p = pred + b * (CC * HW) + hw;
    float v[CC];
    float m = -CUDART_INF_F;
#pragma unroll
    for (int c = 0; c < CC; ++c) {
        v[c] = p[c * HW];
        m = fmaxf(m, v[c]);
    }
    float s = 0.f;
#pragma unroll
    for (int c = 0; c < CC; ++c) s += __expf(v[c] - m);
    const float lse = m + __logf(s);

    // ---- target + gather v[t] without dynamic register indexing ----
    const int* tb = tgt + b * HW;
    const int t = tb[hw];
    float xt = v[0];
#pragma unroll
    for (int c = 1; c < CC; ++c) xt = (t == c) ? v[c] : xt;
    const float ce = lse - xt;

    // ---- edge mask: any in-bounds 3x3 neighbor differs from center ----
    int edge = 0;
#pragma unroll
    for (int dh = -1; dh <= 1; ++dh) {
        const int hh = h + dh;
        if ((unsigned)hh >= (unsigned)HH) continue;
        const int* row = tb + hh * WW;
#pragma unroll
        for (int dw = -1; dw <= 1; ++dw) {
            const int ww = w + dw;
            if ((unsigned)ww >= (unsigned)WW) continue;
            edge |= (row[ww] != t);
        }
    }

    float val = ce * (edge ? 2.0f : 1.0f);

    // ---- block reduction -> g_partials[blockIdx.x] (always overwritten) ----
#pragma unroll
    for (int o = 16; o > 0; o >>= 1) val += __shfl_xor_sync(0xFFFFFFFFu, val, o);

    __shared__ float smem[TPB / 32];
    if ((threadIdx.x & 31) == 0) smem[threadIdx.x >> 5] = val;
    __syncthreads();
    if (threadIdx.x < (TPB / 32)) {
        float x = smem[threadIdx.x];
#pragma unroll
        for (int o = (TPB / 64); o > 0; o >>= 1)
            x += __shfl_xor_sync(0xFFu, x, o);
        if (threadIdx.x == 0) g_partials[blockIdx.x] = x;
    }
}

#define RTPB 1024
#define RPT (NBLK / RTPB)       // 16 partials per thread

__global__ __launch_bounds__(RTPB) void edge_loss_reduce(float* __restrict__ out)
{
    // 16 fully-independent loads per thread (MLP=16), accumulate in double.
    double s = 0.0;
#pragma unroll
    for (int k = 0; k < RPT; ++k)
        s += (double)g_partials[threadIdx.x + k * RTPB];

#pragma unroll
    for (int o = 16; o > 0; o >>= 1) s += __shfl_xor_sync(0xFFFFFFFFu, s, o);

    __shared__ double smem[RTPB / 32];
    if ((threadIdx.x & 31) == 0) smem[threadIdx.x >> 5] = s;
    __syncthreads();
    if (threadIdx.x < 32) {
        double x = smem[threadIdx.x];
#pragma unroll
        for (int o = 16; o > 0; o >>= 1) x += __shfl_xor_sync(0xFFFFFFFFu, x, o);
        if (threadIdx.x == 0) out[0] = (float)(x / (double)NPIX);
    }
}

extern "C" void kernel_launch(void* const* d_in, const int* in_sizes, int n_in,
                              void* d_out, int out_size)
{
    const float* pred = (const float*)d_in[0];
    const int*   tgt  = (const int*)d_in[1];
    float*       out  = (float*)d_out;

    edge_loss_main<<<NBLK, TPB>>>(pred, tgt);
    edge_loss_reduce<<<1, RTPB>>>(out);
}

// round 9
// speedup vs baseline: 1.2049x; 1.1270x over previous
#include <cuda_runtime.h>
#include <cuda_bf16.h>
#include <math_constants.h>

// EdgeAwareLoss: predictions [16,19,512,512] f32, targets [16,512,512] int32
// out: scalar f32 = mean over pixels of CE * (1 + edge)
// edge = any in-bounds 3x3 neighbor label != center label.
//
// Single fused kernel: R4 main body (measured ~55us, ~76% HBM) + last-block
// reduction via fixed-point int64 atomics (associative => deterministic).
// Accumulator/counter reset to 0 by the last block => graph-replay safe.

#define BB 16
#define CC 19
#define HH 512
#define WW 512
#define HW (HH * WW)            // 262144
#define NPIX (BB * HW)          // 4194304
#define TPB 256
#define NBLK (NPIX / TPB)       // 16384
#define FIXSCALE 1048576.0      // 2^20

__device__ unsigned long long g_acc   = 0ULL;
__device__ unsigned int       g_count = 0u;

__global__ __launch_bounds__(TPB) void edge_loss_fused(
    const float* __restrict__ pred, const int* __restrict__ tgt,
    float* __restrict__ out)
{
    const int idx = blockIdx.x * TPB + threadIdx.x;
    const int hw = idx & (HW - 1);
    const int b  = idx >> 18;
    const int h  = hw >> 9;
    const int w  = hw & (WW - 1);

    // ---- channel values: 19 coalesced strided loads, kept in registers ----
    const float* p = pred + b * (CC * HW) + hw;
    float v[CC];
    float m = -CUDART_INF_F;
#pragma unroll
    for (int c = 0; c < CC; ++c) {
        v[c] = p[c * HW];
        m = fmaxf(m, v[c]);
    }
    float s = 0.f;
#pragma unroll
    for (int c = 0; c < CC; ++c) s += __expf(v[c] - m);
    const float lse = m + __logf(s);

    // ---- target + gather v[t] without dynamic register indexing ----
    const int* tb = tgt + b * HW;
    const int t = tb[hw];
    float xt = v[0];
#pragma unroll
    for (int c = 1; c < CC; ++c) xt = (t == c) ? v[c] : xt;
    const float ce = lse - xt;   // always >= 0

    // ---- edge mask: any in-bounds 3x3 neighbor differs from center ----
    int edge = 0;
#pragma unroll
    for (int dh = -1; dh <= 1; ++dh) {
        const int hh = h + dh;
        if ((unsigned)hh >= (unsigned)HH) continue;
        const int* row = tb + hh * WW;
#pragma unroll
        for (int dw = -1; dw <= 1; ++dw) {
            const int ww = w + dw;
            if ((unsigned)ww >= (unsigned)WW) continue;
            edge |= (row[ww] != t);
        }
    }

    float val = ce * (edge ? 2.0f : 1.0f);

    // ---- block reduction ----
#pragma unroll
    for (int o = 16; o > 0; o >>= 1) val += __shfl_xor_sync(0xFFFFFFFFu, val, o);

    __shared__ float smem[TPB / 32];
    if ((threadIdx.x & 31) == 0) smem[threadIdx.x >> 5] = val;
    __syncthreads();

    // ---- fixed-point atomic accumulate + last-block finalize ----
    if (threadIdx.x == 0) {
        float x = 0.f;
#pragma unroll
        for (int i = 0; i < TPB / 32; ++i) x += smem[i];

        const unsigned long long q =
            (unsigned long long)__double2ll_rn((double)x * FIXSCALE);
        atomicAdd(&g_acc, q);
        __threadfence();
        const unsigned int done = atomicAdd(&g_count, 1u);
        if (done == NBLK - 1) {
            // All prior adds are visible (their fence precedes their count inc).
            const unsigned long long tot = atomicAdd(&g_acc, 0ULL);
            out[0] = (float)((double)tot / FIXSCALE / (double)NPIX);
            // Reset for next graph replay (deterministic initial state).
            atomicExch(&g_acc, 0ULL);
            atomicExch(&g_count, 0u);
        }
    }
}

extern "C" void kernel_launch(void* const* d_in, const int* in_sizes, int n_in,
                              void* d_out, int out_size)
{
    const float* pred = (const float*)d_in[0];
    const int*   tgt  = (const int*)d_in[1];
    float*       out  = (float*)d_out;

    edge_loss_fused<<<NBLK, TPB>>>(pred, tgt, out);
}